// round 1
// baseline (speedup 1.0000x reference)
#include <cuda_runtime.h>

#define NB 4
#define NS 1024
#define NHID 1024
#define NH 16
#define NDH 64
#define ATT_SCALE 0.125f

// ---------------- scratch (no allocations allowed) ----------------
__device__ float g_Q[NB * NH * NS * NDH];   // [B,H,S,DH]
__device__ float g_K[NB * NH * NS * NDH];
__device__ float g_V[NB * NH * NS * NDH];
__device__ float g_O[NB * NS * NHID];       // [B,S,H,DH] == [B,S,HID]

// =================================================================
// GEMM 1: projections.  C[b,h,s,e] = sum_d A[b,s,d] * W[h,d,e] + bias[h,e]
// A: [4096,1024] row-major.  W: [16,1024,64].  bias: [1024] flat (h*64+e).
// C written in [B,H,S,DH] layout.
// =================================================================
__global__ __launch_bounds__(256) void gemm_proj(
    const float* __restrict__ A, const float* __restrict__ W,
    const float* __restrict__ bias, float* __restrict__ C)
{
    __shared__ float As[8][128];
    __shared__ float Bs[8][128];
    const int row0 = blockIdx.y * 128;
    const int col0 = blockIdx.x * 128;
    const int tid = threadIdx.x;
    const int tx = tid & 15, ty = tid >> 4;
    const int a_row = tid >> 1;
    const int a_k = (tid & 1) << 2;
    const int b_col = (tid << 2) & 127;
    const int b_k = tid >> 5;
    const int hb = (col0 + b_col) >> 6;
    const int eb = (col0 + b_col) & 63;

    float c[8][8];
#pragma unroll
    for (int i = 0; i < 8; i++)
#pragma unroll
        for (int j = 0; j < 8; j++) c[i][j] = 0.f;

    for (int k0 = 0; k0 < 1024; k0 += 8) {
        float4 av = *(const float4*)&A[(row0 + a_row) * 1024 + k0 + a_k];
        float4 bv = *(const float4*)&W[hb * (1024 * 64) + (k0 + b_k) * 64 + eb];
        __syncthreads();
        As[a_k + 0][a_row] = av.x; As[a_k + 1][a_row] = av.y;
        As[a_k + 2][a_row] = av.z; As[a_k + 3][a_row] = av.w;
        *(float4*)&Bs[b_k][b_col] = bv;
        __syncthreads();
#pragma unroll
        for (int kk = 0; kk < 8; kk++) {
            float4 a0 = *(float4*)&As[kk][ty * 4];
            float4 a1 = *(float4*)&As[kk][ty * 4 + 64];
            float4 b0 = *(float4*)&Bs[kk][tx * 4];
            float4 b1 = *(float4*)&Bs[kk][tx * 4 + 64];
            float ar[8] = {a0.x, a0.y, a0.z, a0.w, a1.x, a1.y, a1.z, a1.w};
            float br[8] = {b0.x, b0.y, b0.z, b0.w, b1.x, b1.y, b1.z, b1.w};
#pragma unroll
            for (int i = 0; i < 8; i++)
#pragma unroll
                for (int j = 0; j < 8; j++) c[i][j] += ar[i] * br[j];
        }
    }
#pragma unroll
    for (int i = 0; i < 8; i++) {
        int row = row0 + ty * 4 + (i & 3) + (i >> 2) * 64;
        int bI = row >> 10, sI = row & 1023;
#pragma unroll
        for (int j = 0; j < 8; j++) {
            int col = col0 + tx * 4 + (j & 3) + (j >> 2) * 64;
            int h = col >> 6, e = col & 63;
            C[((bI * 16 + h) * 1024 + sI) * 64 + e] = c[i][j] + bias[col];
        }
    }
}

// =================================================================
// GEMM 2: fc.  C[r,i] = sum_j A[r,j] * W[i,j] + bias[i]
// =================================================================
__global__ __launch_bounds__(256) void gemm_fc(
    const float* __restrict__ A, const float* __restrict__ W,
    const float* __restrict__ bias, float* __restrict__ C)
{
    __shared__ float As[8][128];
    __shared__ float Bs[8][128];
    const int row0 = blockIdx.y * 128;
    const int col0 = blockIdx.x * 128;
    const int tid = threadIdx.x;
    const int tx = tid & 15, ty = tid >> 4;
    const int a_row = tid >> 1;
    const int a_k = (tid & 1) << 2;
    const int b_col = tid >> 1;
    const int b_k = (tid & 1) << 2;

    float c[8][8];
#pragma unroll
    for (int i = 0; i < 8; i++)
#pragma unroll
        for (int j = 0; j < 8; j++) c[i][j] = 0.f;

    for (int k0 = 0; k0 < 1024; k0 += 8) {
        float4 av = *(const float4*)&A[(row0 + a_row) * 1024 + k0 + a_k];
        float4 bv = *(const float4*)&W[(col0 + b_col) * 1024 + k0 + b_k];
        __syncthreads();
        As[a_k + 0][a_row] = av.x; As[a_k + 1][a_row] = av.y;
        As[a_k + 2][a_row] = av.z; As[a_k + 3][a_row] = av.w;
        Bs[b_k + 0][b_col] = bv.x; Bs[b_k + 1][b_col] = bv.y;
        Bs[b_k + 2][b_col] = bv.z; Bs[b_k + 3][b_col] = bv.w;
        __syncthreads();
#pragma unroll
        for (int kk = 0; kk < 8; kk++) {
            float4 a0 = *(float4*)&As[kk][ty * 4];
            float4 a1 = *(float4*)&As[kk][ty * 4 + 64];
            float4 b0 = *(float4*)&Bs[kk][tx * 4];
            float4 b1 = *(float4*)&Bs[kk][tx * 4 + 64];
            float ar[8] = {a0.x, a0.y, a0.z, a0.w, a1.x, a1.y, a1.z, a1.w};
            float br[8] = {b0.x, b0.y, b0.z, b0.w, b1.x, b1.y, b1.z, b1.w};
#pragma unroll
            for (int i = 0; i < 8; i++)
#pragma unroll
                for (int j = 0; j < 8; j++) c[i][j] += ar[i] * br[j];
        }
    }
#pragma unroll
    for (int i = 0; i < 8; i++) {
        int row = row0 + ty * 4 + (i & 3) + (i >> 2) * 64;
#pragma unroll
        for (int j = 0; j < 8; j++) {
            int col = col0 + tx * 4 + (j & 3) + (j >> 2) * 64;
            C[row * 1024 + col] = c[i][j] + bias[col];
        }
    }
}

// =================================================================
// Fused relation-aware attention. One CTA = (b, h, 32 q-rows).
// Full 32x1024 score strip in SMEM; rel biases via 33-bucket tricks.
// =================================================================
#define BQ 32
#define KT 128
#define PADR 68
#define SMEM_FLOATS (32*1024 + 128*PADR + 32*PADR + 33*PADR + 33*PADR + 32*33 + 32*33 + 32)
#define SMEM_BYTES (SMEM_FLOATS * 4)

__global__ __launch_bounds__(256) void attn_kernel(
    const float* __restrict__ Q, const float* __restrict__ K,
    const float* __restrict__ V, const float* __restrict__ relk,
    const float* __restrict__ relv, float* __restrict__ O)
{
    extern __shared__ float sm[];
    float* sS  = sm;                    // [32][1024] scores -> p (unnormalized)
    float* sKV = sS + 32 * 1024;        // [128][PADR] K or V tile
    float* sQ  = sKV + 128 * PADR;      // [32][PADR]
    float* sRK = sQ + 32 * PADR;        // [33][PADR]
    float* sRV = sRK + 33 * PADR;       // [33][PADR]
    float* sR  = sRV + 33 * PADR;       // [32][33]  q . rel_k_emb[d]
    float* sW  = sR + 32 * 33;          // [32][33]  value-bias buckets
    float* sIL = sW + 32 * 33;          // [32]      1/l

    const int tid = threadIdx.x;
    const int q0 = blockIdx.x * BQ;
    const int bh = blockIdx.z * NH + blockIdx.y;
    const int base = bh * (NS * NDH);

    // ---- load Q tile + rel tables ----
    {
        int idx = tid;
#pragma unroll
        for (int r = 0; r < 2; r++, idx += 256) {
            int row = idx >> 4, e4 = (idx & 15) << 2;
            *(float4*)&sQ[row * PADR + e4] =
                *(const float4*)&Q[base + (q0 + row) * 64 + e4];
        }
    }
    for (int idx = tid; idx < 33 * 16; idx += 256) {
        int row = idx >> 4, e4 = (idx & 15) << 2;
        *(float4*)&sRK[row * PADR + e4] = *(const float4*)&relk[row * 64 + e4];
        *(float4*)&sRV[row * PADR + e4] = *(const float4*)&relv[row * 64 + e4];
    }
    __syncthreads();

    // ---- r[q][d] = q . rel_k_emb[d] ----
    for (int idx = tid; idx < 32 * 33; idx += 256) {
        int q = idx / 33, d = idx - q * 33;
        float s = 0.f;
#pragma unroll
        for (int e = 0; e < 64; e++) s += sQ[q * PADR + e] * sRK[d * PADR + e];
        sR[idx] = s;
    }
    __syncthreads();

    const int tx = tid & 31, ty = tid >> 5;

    // ---- Phase A: scores = (QK^T + rel_k bias) * SCALE ----
    for (int kt = 0; kt < 8; kt++) {
        int k0 = kt * KT;
        float4 tmp[8];
#pragma unroll
        for (int r = 0; r < 8; r++) {
            int idx = tid + 256 * r;
            int row = idx >> 4, e4 = (idx & 15) << 2;
            tmp[r] = *(const float4*)&K[base + (k0 + row) * 64 + e4];
        }
        __syncthreads();
#pragma unroll
        for (int r = 0; r < 8; r++) {
            int idx = tid + 256 * r;
            int row = idx >> 4, e4 = (idx & 15) << 2;
            *(float4*)&sKV[row * PADR + e4] = tmp[r];
        }
        __syncthreads();

        float c[4][4];
#pragma unroll
        for (int i = 0; i < 4; i++)
#pragma unroll
            for (int j = 0; j < 4; j++) c[i][j] = 0.f;
#pragma unroll
        for (int e4 = 0; e4 < 16; e4++) {
            float4 aq[4], bk[4];
#pragma unroll
            for (int i = 0; i < 4; i++)
                aq[i] = *(float4*)&sQ[(4 * ty + i) * PADR + e4 * 4];
#pragma unroll
            for (int j = 0; j < 4; j++)
                bk[j] = *(float4*)&sKV[(tx + 32 * j) * PADR + e4 * 4];
#pragma unroll
            for (int i = 0; i < 4; i++)
#pragma unroll
                for (int j = 0; j < 4; j++)
                    c[i][j] += aq[i].x * bk[j].x + aq[i].y * bk[j].y +
                               aq[i].z * bk[j].z + aq[i].w * bk[j].w;
        }
#pragma unroll
        for (int i = 0; i < 4; i++) {
            int q = 4 * ty + i;
            int qg = q0 + q;
#pragma unroll
            for (int j = 0; j < 4; j++) {
                int kg = k0 + tx + 32 * j;
                int dd = kg - qg;
                dd = dd < -16 ? -16 : (dd > 16 ? 16 : dd);
                sS[q * 1024 + kg] = (c[i][j] + sR[q * 33 + dd + 16]) * ATT_SCALE;
            }
        }
    }
    __syncthreads();

    // ---- Phase B: softmax (unnormalized p, keep 1/l) + edge buckets ----
    {
        int warp = tid >> 5, lane = tid & 31;
        for (int rr = 0; rr < 4; rr++) {
            int r = warp * 4 + rr;
            int qg = q0 + r;
            float m = -1e30f;
            for (int k = lane; k < 1024; k += 32) m = fmaxf(m, sS[r * 1024 + k]);
#pragma unroll
            for (int o = 16; o > 0; o >>= 1)
                m = fmaxf(m, __shfl_xor_sync(0xffffffffu, m, o));
            float l = 0.f, w0 = 0.f, w32 = 0.f;
            for (int k = lane; k < 1024; k += 32) {
                float p = __expf(sS[r * 1024 + k] - m);
                sS[r * 1024 + k] = p;
                l += p;
                if (k <= qg - 16) w0 += p;
                if (k >= qg + 16) w32 += p;
            }
#pragma unroll
            for (int o = 16; o > 0; o >>= 1) {
                l += __shfl_xor_sync(0xffffffffu, l, o);
                w0 += __shfl_xor_sync(0xffffffffu, w0, o);
                w32 += __shfl_xor_sync(0xffffffffu, w32, o);
            }
            if (lane == 0) {
                sIL[r] = 1.f / l;
                sW[r * 33 + 0] = w0;
                sW[r * 33 + 32] = w32;
            }
        }
    }
    __syncthreads();
    // middle buckets d=1..31 are single p values
    for (int idx = tid; idx < 32 * 31; idx += 256) {
        int q = idx / 31, d = idx - q * 31 + 1;
        int k = q0 + q + d - 16;
        sW[q * 33 + d] = (k >= 0 && k < 1024) ? sS[q * 1024 + k] : 0.f;
    }
    __syncthreads();

    // ---- Phase C: out = (p V + w . rel_v_emb) / l ----
    const int cx = tid & 31, cy = tid >> 5;
    float acc[4][2];
#pragma unroll
    for (int i = 0; i < 4; i++) { acc[i][0] = 0.f; acc[i][1] = 0.f; }

    for (int kt = 0; kt < 8; kt++) {
        int k0 = kt * KT;
        float4 tmp[8];
#pragma unroll
        for (int r = 0; r < 8; r++) {
            int idx = tid + 256 * r;
            int row = idx >> 4, e4 = (idx & 15) << 2;
            tmp[r] = *(const float4*)&V[base + (k0 + row) * 64 + e4];
        }
        __syncthreads();
#pragma unroll
        for (int r = 0; r < 8; r++) {
            int idx = tid + 256 * r;
            int row = idx >> 4, e4 = (idx & 15) << 2;
            *(float4*)&sKV[row * PADR + e4] = tmp[r];
        }
        __syncthreads();
#pragma unroll 4
        for (int kk = 0; kk < KT; kk += 4) {
            float4 p4[4];
#pragma unroll
            for (int i = 0; i < 4; i++)
                p4[i] = *(float4*)&sS[(4 * cy + i) * 1024 + k0 + kk];
            float v0[4], v1[4];
#pragma unroll
            for (int u = 0; u < 4; u++) {
                v0[u] = sKV[(kk + u) * PADR + cx];
                v1[u] = sKV[(kk + u) * PADR + cx + 32];
            }
#pragma unroll
            for (int i = 0; i < 4; i++) {
                acc[i][0] += p4[i].x * v0[0] + p4[i].y * v0[1] +
                             p4[i].z * v0[2] + p4[i].w * v0[3];
                acc[i][1] += p4[i].x * v1[0] + p4[i].y * v1[1] +
                             p4[i].z * v1[2] + p4[i].w * v1[3];
            }
        }
    }

    // rel_v bias + normalize + write O in [B,S,H,DH]
#pragma unroll
    for (int i = 0; i < 4; i++) {
        int q = 4 * cy + i;
        float a0 = acc[i][0], a1 = acc[i][1];
#pragma unroll
        for (int d = 0; d < 33; d++) {
            float wv = sW[q * 33 + d];
            a0 += wv * sRV[d * PADR + cx];
            a1 += wv * sRV[d * PADR + cx + 32];
        }
        float il = sIL[q];
        int qg = q0 + q;
        int o = ((blockIdx.z * 1024 + qg) * 16 + blockIdx.y) * 64;
        O[o + cx] = a0 * il;
        O[o + cx + 32] = a1 * il;
    }
}

// =================================================================
extern "C" void kernel_launch(void* const* d_in, const int* in_sizes, int n_in,
                              void* d_out, int out_size)
{
    const float* query = (const float*)d_in[0];
    const float* key   = (const float*)d_in[1];
    const float* value = (const float*)d_in[2];
    const float* Wq    = (const float*)d_in[3];
    const float* bq    = (const float*)d_in[4];
    const float* Wk    = (const float*)d_in[5];
    const float* bk    = (const float*)d_in[6];
    const float* Wv    = (const float*)d_in[7];
    const float* bv    = (const float*)d_in[8];
    const float* relk  = (const float*)d_in[9];
    const float* relv  = (const float*)d_in[10];
    const float* fcW   = (const float*)d_in[11];
    const float* fcb   = (const float*)d_in[12];
    float* out = (float*)d_out;

    float *Qp, *Kp, *Vp, *Op;
    cudaGetSymbolAddress((void**)&Qp, g_Q);
    cudaGetSymbolAddress((void**)&Kp, g_K);
    cudaGetSymbolAddress((void**)&Vp, g_V);
    cudaGetSymbolAddress((void**)&Op, g_O);

    dim3 gg(1024 / 128, 4096 / 128);
    gemm_proj<<<gg, 256>>>(query, Wq, bq, Qp);
    gemm_proj<<<gg, 256>>>(key,   Wk, bk, Kp);
    gemm_proj<<<gg, 256>>>(value, Wv, bv, Vp);

    cudaFuncSetAttribute(attn_kernel,
                         cudaFuncAttributeMaxDynamicSharedMemorySize, SMEM_BYTES);
    attn_kernel<<<dim3(NS / BQ, NH, NB), 256, SMEM_BYTES>>>(Qp, Kp, Vp, relk, relv, Op);

    gemm_fc<<<gg, 256>>>(Op, fcW, fcb, out);
}

// round 3
// speedup vs baseline: 1.3247x; 1.3247x over previous
#include <cuda_runtime.h>
#include <cuda_bf16.h>
#include <cstdint>

#define NB 4
#define NS 1024
#define NHID 1024
#define NH 16
#define NDH 64
#define ATT_SCALE 0.125f

// ---------------- scratch (no allocations allowed) ----------------
__device__ float g_Q[NB * NH * NS * NDH];   // [B,H,S,DH]
__device__ float g_K[NB * NH * NS * NDH];
__device__ float g_V[NB * NH * NS * NDH];
__device__ float g_O[NB * NS * NHID];       // [B,S,H,DH] == [B,S,HID]
__device__ __nv_bfloat16 g_Ah[4096 * 1024];
__device__ __nv_bfloat16 g_Al[4096 * 1024];
__device__ __nv_bfloat16 g_Bh[1024 * 1024];
__device__ __nv_bfloat16 g_Bl[1024 * 1024];

// =================================================================
// helpers
// =================================================================
__device__ __forceinline__ uint32_t smem_u32(const void* p) {
    uint32_t a;
    asm("{ .reg .u64 t; cvta.to.shared.u64 t, %1; cvt.u32.u64 %0, t; }"
        : "=r"(a) : "l"(p));
    return a;
}
#define CP_ASYNC16(sp, gp) \
    asm volatile("cp.async.cg.shared.global [%0], [%1], 16;" :: "r"(sp), "l"(gp) : "memory")
#define CP_COMMIT() asm volatile("cp.async.commit_group;" ::: "memory")
#define CP_WAIT(n)  asm volatile("cp.async.wait_group %0;" :: "n"(n) : "memory")
#define LDSM4(r, a) \
    asm volatile("ldmatrix.sync.aligned.m8n8.x4.shared.b16 {%0,%1,%2,%3}, [%4];" \
                 : "=r"((r)[0]), "=r"((r)[1]), "=r"((r)[2]), "=r"((r)[3]) : "r"(a))

__device__ __forceinline__ void mma_bf16(float* d, const uint32_t* a, const uint32_t* b) {
    asm volatile(
        "mma.sync.aligned.m16n8k16.row.col.f32.bf16.bf16.f32 "
        "{%0,%1,%2,%3},{%4,%5,%6,%7},{%8,%9},{%0,%1,%2,%3};"
        : "+f"(d[0]), "+f"(d[1]), "+f"(d[2]), "+f"(d[3])
        : "r"(a[0]), "r"(a[1]), "r"(a[2]), "r"(a[3]), "r"(b[0]), "r"(b[1]));
}

__device__ __forceinline__ void split2(float v, __nv_bfloat16& h, __nv_bfloat16& l) {
    h = __float2bfloat16_rn(v);
    l = __float2bfloat16_rn(v - __bfloat162float(h));
}

// =================================================================
// conversion kernels: fp32 -> bf16 hi/lo
// =================================================================
__global__ __launch_bounds__(256) void split_f32(
    const float* __restrict__ A, __nv_bfloat16* __restrict__ H,
    __nv_bfloat16* __restrict__ L, int n)
{
    int i = (blockIdx.x * 256 + threadIdx.x) * 4;
    if (i >= n) return;
    float4 v = *(const float4*)&A[i];
    __nv_bfloat16 h[4], l[4];
    split2(v.x, h[0], l[0]); split2(v.y, h[1], l[1]);
    split2(v.z, h[2], l[2]); split2(v.w, h[3], l[3]);
    *(uint2*)&H[i] = *(uint2*)h;
    *(uint2*)&L[i] = *(uint2*)l;
}

// W[h][k][e] fp32 -> Wt[h*64+e][k] bf16 hi/lo (transpose + split)
__global__ __launch_bounds__(256) void splitW_proj(
    const float* __restrict__ W, __nv_bfloat16* __restrict__ Ht,
    __nv_bfloat16* __restrict__ Lt)
{
    __shared__ float t[32][33];
    const int k0 = blockIdx.x * 32;
    const int n0 = blockIdx.y * 32;
    const int h = n0 >> 6, e0 = n0 & 63;
    const int x = threadIdx.x & 31, y = threadIdx.x >> 5;
#pragma unroll
    for (int j = 0; j < 32; j += 8)
        t[y + j][x] = W[h * 65536 + (k0 + y + j) * 64 + e0 + x];
    __syncthreads();
#pragma unroll
    for (int j = 0; j < 32; j += 8) {
        float v = t[x][y + j];
        __nv_bfloat16 hi, lo;
        split2(v, hi, lo);
        size_t o = (size_t)(n0 + y + j) * 1024 + k0 + x;
        Ht[o] = hi;
        Lt[o] = lo;
    }
}

// =================================================================
// HMMA GEMM: C[4096x1024] = A x B^T + bias  (A [m][k], B [n][k], bf16 split)
// MODE 0: C row-major.  MODE 1: C[((b*16+h)*1024+s)*64+e]
// =================================================================
#define BK 32
#define PADE 40                   // padded row stride in bf16 elems (80 B)
#define TILE_E (128 * PADE)       // elems per tile matrix
#define TILE_B (TILE_E * 2)       // bytes
#define GH_SMEM (8 * TILE_B)      // 4 matrices x 2 stages = 81920 B

template <int MODE>
__global__ __launch_bounds__(256) void gemm_hmma(
    const __nv_bfloat16* __restrict__ Ah, const __nv_bfloat16* __restrict__ Al,
    const __nv_bfloat16* __restrict__ Bh, const __nv_bfloat16* __restrict__ Bl,
    const float* __restrict__ bias, float* __restrict__ C)
{
    extern __shared__ __align__(128) char gsm[];
    const uint32_t sb = smem_u32(gsm);
    const int tid = threadIdx.x;
    const int m0 = blockIdx.y * 128;
    const int n0 = blockIdx.x * 128;
    const int lane = tid & 31, w = tid >> 5;
    const int wm = w >> 2;   // 0..1
    const int wn = w & 3;    // 0..3
    const int lr = lane & 15;
    const int lcb = (lane >> 4) * 16;  // col chunk byte offset (0/16)

    const __nv_bfloat16* gmat[4] = {Ah, Al, Bh, Bl};
    const int rbase[4] = {m0, m0, n0, n0};

    float acc[4][4][4];
#pragma unroll
    for (int i = 0; i < 4; i++)
#pragma unroll
        for (int j = 0; j < 4; j++)
#pragma unroll
            for (int r = 0; r < 4; r++) acc[i][j][r] = 0.f;

    // precomputed ldmatrix byte offsets within a tile
    uint32_t aoff[4], boff[2];
#pragma unroll
    for (int i = 0; i < 4; i++)
        aoff[i] = (uint32_t)((wm * 64 + i * 16 + lr) * 80) + lcb;
#pragma unroll
    for (int hlf = 0; hlf < 2; hlf++)
        boff[hlf] = (uint32_t)((wn * 32 + hlf * 16 + lr) * 80) + lcb;

    // ---- stage loader ----
    auto load_stage = [&](int s) {
        const int buf = s & 1;
        const int k0 = s * BK;
#pragma unroll
        for (int mat = 0; mat < 4; mat++) {
            const __nv_bfloat16* g = gmat[mat];
            uint32_t sbase = sb + (uint32_t)(buf * 4 + mat) * TILE_B;
#pragma unroll
            for (int i = 0; i < 2; i++) {
                int idx = tid + 256 * i;        // 0..511
                int row = idx >> 2;             // 0..127
                int ch = idx & 3;               // 16B chunk
                const void* gp = g + (size_t)(rbase[mat] + row) * 1024 + k0 + ch * 8;
                uint32_t sp = sbase + (uint32_t)(row * 80 + ch * 16);
                CP_ASYNC16(sp, gp);
            }
        }
        CP_COMMIT();
    };

    load_stage(0);

    for (int s = 0; s < 32; s++) {
        if (s + 1 < 32) {
            load_stage(s + 1);
            CP_WAIT(1);
        } else {
            CP_WAIT(0);
        }
        __syncthreads();

        const int buf = s & 1;
        const uint32_t base = sb + (uint32_t)buf * 4 * TILE_B;
#pragma unroll
        for (int kk = 0; kk < 2; kk++) {
            const uint32_t kb = kk * 32;  // 16 elems = 32 bytes
            uint32_t ah[4][4], al[4][4];
#pragma unroll
            for (int i = 0; i < 4; i++) {
                LDSM4(ah[i], base + aoff[i] + kb);
                LDSM4(al[i], base + TILE_B + aoff[i] + kb);
            }
            uint32_t bh[4][2], bl[4][2];
#pragma unroll
            for (int hlf = 0; hlf < 2; hlf++) {
                uint32_t r[4];
                LDSM4(r, base + 2 * TILE_B + boff[hlf] + kb);
                bh[2 * hlf][0] = r[0]; bh[2 * hlf + 1][0] = r[1];
                bh[2 * hlf][1] = r[2]; bh[2 * hlf + 1][1] = r[3];
                LDSM4(r, base + 3 * TILE_B + boff[hlf] + kb);
                bl[2 * hlf][0] = r[0]; bl[2 * hlf + 1][0] = r[1];
                bl[2 * hlf][1] = r[2]; bl[2 * hlf + 1][1] = r[3];
            }
#pragma unroll
            for (int i = 0; i < 4; i++)
#pragma unroll
                for (int j = 0; j < 4; j++) {
                    mma_bf16(acc[i][j], ah[i], bh[j]);
                    mma_bf16(acc[i][j], ah[i], bl[j]);
                    mma_bf16(acc[i][j], al[i], bh[j]);
                }
        }
        __syncthreads();
    }

    // ---- epilogue ----
#pragma unroll
    for (int i = 0; i < 4; i++) {
#pragma unroll
        for (int j = 0; j < 4; j++) {
            int row = m0 + wm * 64 + i * 16 + (lane >> 2);
            int col = n0 + wn * 32 + j * 8 + (lane & 3) * 2;
            float b0 = bias[col], b1 = bias[col + 1];
            float2 v0 = make_float2(acc[i][j][0] + b0, acc[i][j][1] + b1);
            float2 v1 = make_float2(acc[i][j][2] + b0, acc[i][j][3] + b1);
            if (MODE == 0) {
                *(float2*)&C[(size_t)row * 1024 + col] = v0;
                *(float2*)&C[(size_t)(row + 8) * 1024 + col] = v1;
            } else {
                int h = col >> 6, e = col & 63;
                int b = row >> 10, sI = row & 1023;
                int b2 = (row + 8) >> 10, s2 = (row + 8) & 1023;
                *(float2*)&C[(((size_t)(b * 16 + h) * 1024 + sI) << 6) + e] = v0;
                *(float2*)&C[(((size_t)(b2 * 16 + h) * 1024 + s2) << 6) + e] = v1;
            }
        }
    }
}

// =================================================================
// Fused relation-aware attention (unchanged from round 1).
// =================================================================
#define BQ 32
#define KT 128
#define PADR 68
#define SMEM_FLOATS (32*1024 + 128*PADR + 32*PADR + 33*PADR + 33*PADR + 32*33 + 32*33 + 32)
#define SMEM_BYTES (SMEM_FLOATS * 4)

__global__ __launch_bounds__(256) void attn_kernel(
    const float* __restrict__ Q, const float* __restrict__ K,
    const float* __restrict__ V, const float* __restrict__ relk,
    const float* __restrict__ relv, float* __restrict__ O)
{
    extern __shared__ float sm[];
    float* sS  = sm;
    float* sKV = sS + 32 * 1024;
    float* sQ  = sKV + 128 * PADR;
    float* sRK = sQ + 32 * PADR;
    float* sRV = sRK + 33 * PADR;
    float* sR  = sRV + 33 * PADR;
    float* sW  = sR + 32 * 33;
    float* sIL = sW + 32 * 33;

    const int tid = threadIdx.x;
    const int q0 = blockIdx.x * BQ;
    const int bh = blockIdx.z * NH + blockIdx.y;
    const int base = bh * (NS * NDH);

    {
        int idx = tid;
#pragma unroll
        for (int r = 0; r < 2; r++, idx += 256) {
            int row = idx >> 4, e4 = (idx & 15) << 2;
            *(float4*)&sQ[row * PADR + e4] =
                *(const float4*)&Q[base + (q0 + row) * 64 + e4];
        }
    }
    for (int idx = tid; idx < 33 * 16; idx += 256) {
        int row = idx >> 4, e4 = (idx & 15) << 2;
        *(float4*)&sRK[row * PADR + e4] = *(const float4*)&relk[row * 64 + e4];
        *(float4*)&sRV[row * PADR + e4] = *(const float4*)&relv[row * 64 + e4];
    }
    __syncthreads();

    for (int idx = tid; idx < 32 * 33; idx += 256) {
        int q = idx / 33, d = idx - q * 33;
        float s = 0.f;
#pragma unroll
        for (int e = 0; e < 64; e++) s += sQ[q * PADR + e] * sRK[d * PADR + e];
        sR[idx] = s;
    }
    __syncthreads();

    const int tx = tid & 31, ty = tid >> 5;

    for (int kt = 0; kt < 8; kt++) {
        int k0 = kt * KT;
        float4 tmp[8];
#pragma unroll
        for (int r = 0; r < 8; r++) {
            int idx = tid + 256 * r;
            int row = idx >> 4, e4 = (idx & 15) << 2;
            tmp[r] = *(const float4*)&K[base + (k0 + row) * 64 + e4];
        }
        __syncthreads();
#pragma unroll
        for (int r = 0; r < 8; r++) {
            int idx = tid + 256 * r;
            int row = idx >> 4, e4 = (idx & 15) << 2;
            *(float4*)&sKV[row * PADR + e4] = tmp[r];
        }
        __syncthreads();

        float c[4][4];
#pragma unroll
        for (int i = 0; i < 4; i++)
#pragma unroll
            for (int j = 0; j < 4; j++) c[i][j] = 0.f;
#pragma unroll
        for (int e4 = 0; e4 < 16; e4++) {
            float4 aq[4], bk[4];
#pragma unroll
            for (int i = 0; i < 4; i++)
                aq[i] = *(float4*)&sQ[(4 * ty + i) * PADR + e4 * 4];
#pragma unroll
            for (int j = 0; j < 4; j++)
                bk[j] = *(float4*)&sKV[(tx + 32 * j) * PADR + e4 * 4];
#pragma unroll
            for (int i = 0; i < 4; i++)
#pragma unroll
                for (int j = 0; j < 4; j++)
                    c[i][j] += aq[i].x * bk[j].x + aq[i].y * bk[j].y +
                               aq[i].z * bk[j].z + aq[i].w * bk[j].w;
        }
#pragma unroll
        for (int i = 0; i < 4; i++) {
            int q = 4 * ty + i;
            int qg = q0 + q;
#pragma unroll
            for (int j = 0; j < 4; j++) {
                int kg = k0 + tx + 32 * j;
                int dd = kg - qg;
                dd = dd < -16 ? -16 : (dd > 16 ? 16 : dd);
                sS[q * 1024 + kg] = (c[i][j] + sR[q * 33 + dd + 16]) * ATT_SCALE;
            }
        }
    }
    __syncthreads();

    {
        int warp = tid >> 5, lane = tid & 31;
        for (int rr = 0; rr < 4; rr++) {
            int r = warp * 4 + rr;
            int qg = q0 + r;
            float m = -1e30f;
            for (int k = lane; k < 1024; k += 32) m = fmaxf(m, sS[r * 1024 + k]);
#pragma unroll
            for (int o = 16; o > 0; o >>= 1)
                m = fmaxf(m, __shfl_xor_sync(0xffffffffu, m, o));
            float l = 0.f, w0 = 0.f, w32 = 0.f;
            for (int k = lane; k < 1024; k += 32) {
                float p = __expf(sS[r * 1024 + k] - m);
                sS[r * 1024 + k] = p;
                l += p;
                if (k <= qg - 16) w0 += p;
                if (k >= qg + 16) w32 += p;
            }
#pragma unroll
            for (int o = 16; o > 0; o >>= 1) {
                l += __shfl_xor_sync(0xffffffffu, l, o);
                w0 += __shfl_xor_sync(0xffffffffu, w0, o);
                w32 += __shfl_xor_sync(0xffffffffu, w32, o);
            }
            if (lane == 0) {
                sIL[r] = 1.f / l;
                sW[r * 33 + 0] = w0;
                sW[r * 33 + 32] = w32;
            }
        }
    }
    __syncthreads();
    for (int idx = tid; idx < 32 * 31; idx += 256) {
        int q = idx / 31, d = idx - q * 31 + 1;
        int k = q0 + q + d - 16;
        sW[q * 33 + d] = (k >= 0 && k < 1024) ? sS[q * 1024 + k] : 0.f;
    }
    __syncthreads();

    const int cx = tid & 31, cy = tid >> 5;
    float acc[4][2];
#pragma unroll
    for (int i = 0; i < 4; i++) { acc[i][0] = 0.f; acc[i][1] = 0.f; }

    for (int kt = 0; kt < 8; kt++) {
        int k0 = kt * KT;
        float4 tmp[8];
#pragma unroll
        for (int r = 0; r < 8; r++) {
            int idx = tid + 256 * r;
            int row = idx >> 4, e4 = (idx & 15) << 2;
            tmp[r] = *(const float4*)&V[base + (k0 + row) * 64 + e4];
        }
        __syncthreads();
#pragma unroll
        for (int r = 0; r < 8; r++) {
            int idx = tid + 256 * r;
            int row = idx >> 4, e4 = (idx & 15) << 2;
            *(float4*)&sKV[row * PADR + e4] = tmp[r];
        }
        __syncthreads();
#pragma unroll 4
        for (int kk = 0; kk < KT; kk += 4) {
            float4 p4[4];
#pragma unroll
            for (int i = 0; i < 4; i++)
                p4[i] = *(float4*)&sS[(4 * cy + i) * 1024 + k0 + kk];
            float v0[4], v1[4];
#pragma unroll
            for (int u = 0; u < 4; u++) {
                v0[u] = sKV[(kk + u) * PADR + cx];
                v1[u] = sKV[(kk + u) * PADR + cx + 32];
            }
#pragma unroll
            for (int i = 0; i < 4; i++) {
                acc[i][0] += p4[i].x * v0[0] + p4[i].y * v0[1] +
                             p4[i].z * v0[2] + p4[i].w * v0[3];
                acc[i][1] += p4[i].x * v1[0] + p4[i].y * v1[1] +
                             p4[i].z * v1[2] + p4[i].w * v1[3];
            }
        }
    }

#pragma unroll
    for (int i = 0; i < 4; i++) {
        int q = 4 * cy + i;
        float a0 = acc[i][0], a1 = acc[i][1];
#pragma unroll
        for (int d = 0; d < 33; d++) {
            float wv = sW[q * 33 + d];
            a0 += wv * sRV[d * PADR + cx];
            a1 += wv * sRV[d * PADR + cx + 32];
        }
        float il = sIL[q];
        int qg = q0 + q;
        int o = ((blockIdx.z * 1024 + qg) * 16 + blockIdx.y) * 64;
        O[o + cx] = a0 * il;
        O[o + cx + 32] = a1 * il;
    }
}

// =================================================================
extern "C" void kernel_launch(void* const* d_in, const int* in_sizes, int n_in,
                              void* d_out, int out_size)
{
    const float* query = (const float*)d_in[0];
    const float* key   = (const float*)d_in[1];
    const float* value = (const float*)d_in[2];
    const float* Wq    = (const float*)d_in[3];
    const float* bq    = (const float*)d_in[4];
    const float* Wk    = (const float*)d_in[5];
    const float* bk    = (const float*)d_in[6];
    const float* Wv    = (const float*)d_in[7];
    const float* bv    = (const float*)d_in[8];
    const float* relk  = (const float*)d_in[9];
    const float* relv  = (const float*)d_in[10];
    const float* fcW   = (const float*)d_in[11];
    const float* fcb   = (const float*)d_in[12];
    float* out = (float*)d_out;

    float *Qp, *Kp, *Vp, *Op;
    __nv_bfloat16 *Ah, *Al, *Bh, *Bl;
    cudaGetSymbolAddress((void**)&Qp, g_Q);
    cudaGetSymbolAddress((void**)&Kp, g_K);
    cudaGetSymbolAddress((void**)&Vp, g_V);
    cudaGetSymbolAddress((void**)&Op, g_O);
    cudaGetSymbolAddress((void**)&Ah, g_Ah);
    cudaGetSymbolAddress((void**)&Al, g_Al);
    cudaGetSymbolAddress((void**)&Bh, g_Bh);
    cudaGetSymbolAddress((void**)&Bl, g_Bl);

    cudaFuncSetAttribute(gemm_hmma<0>,
                         cudaFuncAttributeMaxDynamicSharedMemorySize, GH_SMEM);
    cudaFuncSetAttribute(gemm_hmma<1>,
                         cudaFuncAttributeMaxDynamicSharedMemorySize, GH_SMEM);
    cudaFuncSetAttribute(attn_kernel,
                         cudaFuncAttributeMaxDynamicSharedMemorySize, SMEM_BYTES);

    dim3 gg(8, 32);
    dim3 tw(32, 32);

    // Q = query @ Wq + bq
    splitW_proj<<<tw, 256>>>(Wq, Bh, Bl);
    split_f32<<<4096, 256>>>(query, Ah, Al, 4096 * 1024);
    gemm_hmma<1><<<gg, 256, GH_SMEM>>>(Ah, Al, Bh, Bl, bq, Qp);

    // K
    splitW_proj<<<tw, 256>>>(Wk, Bh, Bl);
    split_f32<<<4096, 256>>>(key, Ah, Al, 4096 * 1024);
    gemm_hmma<1><<<gg, 256, GH_SMEM>>>(Ah, Al, Bh, Bl, bk, Kp);

    // V
    splitW_proj<<<tw, 256>>>(Wv, Bh, Bl);
    split_f32<<<4096, 256>>>(value, Ah, Al, 4096 * 1024);
    gemm_hmma<1><<<gg, 256, GH_SMEM>>>(Ah, Al, Bh, Bl, bv, Vp);

    // attention
    attn_kernel<<<dim3(NS / BQ, NH, NB), 256, SMEM_BYTES>>>(Qp, Kp, Vp, relk, relv, Op);

    // fc: out = O @ fcW^T + fcb   (fcW is [n][k] row-major already)
    split_f32<<<1024, 256>>>(fcW, Bh, Bl, 1024 * 1024);
    split_f32<<<4096, 256>>>(Op, Ah, Al, 4096 * 1024);
    gemm_hmma<0><<<gg, 256, GH_SMEM>>>(Ah, Al, Bh, Bl, fcb, out);
}